// round 4
// baseline (speedup 1.0000x reference)
#include <cuda_runtime.h>
#include <math.h>

#define BATCH 2
#define SEQ   2048
#define NH    16
#define HD    128
#define HID   2048
#define NQKV  6144
#define MROWS 4096   // B*S

// ---------------- scratch (static device globals; no runtime alloc) ----------
__device__ float g_q[(size_t)BATCH * NH * SEQ * HD];
__device__ float g_k[(size_t)BATCH * NH * SEQ * HD];
__device__ float g_v[(size_t)BATCH * NH * SEQ * HD];
__device__ float g_ctx[(size_t)MROWS * HID];
__device__ float g_cos[SEQ * 64];
__device__ float g_sin[SEQ * 64];

// ---------------- RoPE tables ------------------------------------------------
__global__ void rope_table_kernel() {
    int idx = blockIdx.x * 256 + threadIdx.x;
    if (idx >= SEQ * 64) return;
    int s = idx >> 6, i = idx & 63;
    float inv = powf(10000.0f, -(float)(2 * i) / 128.0f);
    float ang = (float)s * inv;
    g_cos[idx] = cosf(ang);
    g_sin[idx] = sinf(ang);
}

// ---------------- QKV GEMM: [4096,2048] @ W^T[2048,6144] + bias, fused RoPE --
__global__ __launch_bounds__(256) void qkv_gemm_kernel(
    const float* __restrict__ A, const float* __restrict__ W,
    const float* __restrict__ bias) {
    __shared__ float As[16][132];
    __shared__ float Bs[16][132];
    const int tid = threadIdx.x;
    const int tx = tid & 15, ty = tid >> 4;
    const int bm = blockIdx.y * 128, bn = blockIdx.x * 128;

    float acc[8][8];
#pragma unroll
    for (int i = 0; i < 8; i++)
#pragma unroll
        for (int j = 0; j < 8; j++) acc[i][j] = 0.0f;

    for (int k0 = 0; k0 < HID; k0 += 16) {
#pragma unroll
        for (int it = 0; it < 2; it++) {
            int f = tid * 2 + it;          // 0..511
            int m = f >> 2;                // tile row 0..127
            int kq = (f & 3) << 2;         // 0,4,8,12
            float4 a = *(const float4*)(A + (size_t)(bm + m) * HID + k0 + kq);
            As[kq + 0][m] = a.x; As[kq + 1][m] = a.y;
            As[kq + 2][m] = a.z; As[kq + 3][m] = a.w;
            float4 b = *(const float4*)(W + (size_t)(bn + m) * HID + k0 + kq);
            Bs[kq + 0][m] = b.x; Bs[kq + 1][m] = b.y;
            Bs[kq + 2][m] = b.z; Bs[kq + 3][m] = b.w;
        }
        __syncthreads();
#pragma unroll
        for (int kk = 0; kk < 16; kk++) {
            float ra[8], rb[8];
            *(float4*)(ra)     = *(float4*)&As[kk][ty * 8];
            *(float4*)(ra + 4) = *(float4*)&As[kk][ty * 8 + 4];
            *(float4*)(rb)     = *(float4*)&Bs[kk][tx * 8];
            *(float4*)(rb + 4) = *(float4*)&Bs[kk][tx * 8 + 4];
#pragma unroll
            for (int i = 0; i < 8; i++)
#pragma unroll
                for (int j = 0; j < 8; j++)
                    acc[i][j] = fmaf(ra[i], rb[j], acc[i][j]);
        }
        __syncthreads();
    }

    // epilogue: bias + RoPE (q,k) + scatter to [B,H,S,D]
    const int n0 = bn + tx * 8;            // column in [0,6144)
    const int seg = n0 >> 11;              // 0=q 1=k 2=v
    const int h = (n0 & 2047) >> 7;
    const int d0 = n0 & 127;               // even, 8-aligned
    float bv[8];
#pragma unroll
    for (int j = 0; j < 8; j++) bv[j] = bias[n0 + j];

#pragma unroll
    for (int i = 0; i < 8; i++) {
        int gm = bm + ty * 8 + i;
        int b = gm >> 11, s = gm & 2047;
        float vals[8];
#pragma unroll
        for (int j = 0; j < 8; j++) vals[j] = acc[i][j] + bv[j];
        float* dst;
        if (seg < 2) {
#pragma unroll
            for (int t = 0; t < 4; t++) {
                int fi = (d0 >> 1) + t;
                float c  = g_cos[s * 64 + fi];
                float sn = g_sin[s * 64 + fi];
                float e = vals[2 * t], o = vals[2 * t + 1];
                vals[2 * t]     = e * c - o * sn;
                vals[2 * t + 1] = e * sn + o * c;
            }
            dst = (seg == 0) ? g_q : g_k;
        } else {
            dst = g_v;
        }
        size_t off = (((size_t)b * NH + h) * SEQ + s) * HD + d0;
        *(float4*)(dst + off)     = *(float4*)(vals);
        *(float4*)(dst + off + 4) = *(float4*)(vals + 4);
    }
}

// ---------------- Flash attention: Br=64, Bc=64, D=128, online softmax -------
__global__ __launch_bounds__(256) void attn_kernel(const float* __restrict__ mask) {
    extern __shared__ float sm[];
    float* Qst = sm;                  // [128][68] transposed (d-major)
    float* Kst = Qst + 128 * 68;      // [128][68] transposed
    float* Vs  = Kst + 128 * 68;      // [64][128] natural
    float* Ss  = Vs + 64 * 128;       // [64][68]
    float* s_m = Ss + 64 * 68;        // [64]
    float* s_l = s_m + 64;            // [64]
    float* s_al = s_l + 64;           // [64]

    const int tid = threadIdx.x;
    const int q0 = blockIdx.x * 64;
    const int h = blockIdx.y, b = blockIdx.z;
    const size_t head_base = ((size_t)b * NH + h) * SEQ * HD;
    const float scale = 0.08838834764831845f; // 1/sqrt(128)

    // load Q transposed (once per block)
    for (int f = tid; f < 64 * 32; f += 256) {
        int r = f & 63;
        int d = (f >> 6) << 2;
        float4 q = *(const float4*)(g_q + head_base + (size_t)(q0 + r) * HD + d);
        Qst[(d + 0) * 68 + r] = q.x; Qst[(d + 1) * 68 + r] = q.y;
        Qst[(d + 2) * 68 + r] = q.z; Qst[(d + 3) * 68 + r] = q.w;
    }
    if (tid < 64) { s_m[tid] = -INFINITY; s_l[tid] = 0.0f; }

    float o[4][8];
#pragma unroll
    for (int i = 0; i < 4; i++)
#pragma unroll
        for (int j = 0; j < 8; j++) o[i][j] = 0.0f;

    const int sy = tid >> 4, sx = tid & 15;     // S rows sy*4.., S cols sx*4.. ; PV cols sx*8..
    const int srow = tid >> 2, sq = tid & 3;    // softmax: 4 threads per row
    const float* mrow = mask + (size_t)b * SEQ;

    for (int k0 = 0; k0 < SEQ; k0 += 64) {
        __syncthreads();  // previous PV done before overwriting K/V/S
        // load K transposed
        for (int f = tid; f < 64 * 32; f += 256) {
            int r = f & 63;
            int d = (f >> 6) << 2;
            float4 kv = *(const float4*)(g_k + head_base + (size_t)(k0 + r) * HD + d);
            Kst[(d + 0) * 68 + r] = kv.x; Kst[(d + 1) * 68 + r] = kv.y;
            Kst[(d + 2) * 68 + r] = kv.z; Kst[(d + 3) * 68 + r] = kv.w;
        }
        // load V natural
        for (int f = tid; f < 64 * 32; f += 256) {
            int r = f >> 5;
            int d = (f & 31) << 2;
            *(float4*)(Vs + r * 128 + d) =
                *(const float4*)(g_v + head_base + (size_t)(k0 + r) * HD + d);
        }
        __syncthreads();

        // S = Q @ K^T  (4x4 per thread)
        float acc[4][4];
#pragma unroll
        for (int i = 0; i < 4; i++)
#pragma unroll
            for (int j = 0; j < 4; j++) acc[i][j] = 0.0f;
#pragma unroll 4
        for (int kk = 0; kk < 128; kk++) {
            float ra[4], rb[4];
            *(float4*)ra = *(float4*)(Qst + kk * 68 + sy * 4);
            *(float4*)rb = *(float4*)(Kst + kk * 68 + sx * 4);
#pragma unroll
            for (int i = 0; i < 4; i++)
#pragma unroll
                for (int j = 0; j < 4; j++)
                    acc[i][j] = fmaf(ra[i], rb[j], acc[i][j]);
        }
#pragma unroll
        for (int i = 0; i < 4; i++)
#pragma unroll
            for (int j = 0; j < 4; j++)
                Ss[(sy * 4 + i) * 68 + sx * 4 + j] =
                    acc[i][j] * scale + mrow[k0 + sx * 4 + j];
        __syncthreads();

        // online softmax: 4 threads per row, 16 cols each
        {
            float* srp = Ss + srow * 68 + sq * 16;
            float mloc = -INFINITY;
#pragma unroll
            for (int c = 0; c < 16; c++) mloc = fmaxf(mloc, srp[c]);
            mloc = fmaxf(mloc, __shfl_xor_sync(0xffffffffu, mloc, 1));
            mloc = fmaxf(mloc, __shfl_xor_sync(0xffffffffu, mloc, 2));
            float m_old = s_m[srow];
            float m_new = fmaxf(m_old, mloc);
            float sum = 0.0f;
#pragma unroll
            for (int c = 0; c < 16; c++) {
                float p = __expf(srp[c] - m_new);
                srp[c] = p;
                sum += p;
            }
            sum += __shfl_xor_sync(0xffffffffu, sum, 1);
            sum += __shfl_xor_sync(0xffffffffu, sum, 2);
            if (sq == 0) {
                float alpha = __expf(m_old - m_new);
                s_al[srow] = alpha;
                s_m[srow] = m_new;
                s_l[srow] = s_l[srow] * alpha + sum;
            }
        }
        __syncthreads();

        // rescale O, then O += P @ V
#pragma unroll
        for (int i = 0; i < 4; i++) {
            float a = s_al[sy * 4 + i];
#pragma unroll
            for (int j = 0; j < 8; j++) o[i][j] *= a;
        }
#pragma unroll 2
        for (int kk = 0; kk < 64; kk++) {
            float rv[8];
            *(float4*)(rv)     = *(float4*)(Vs + kk * 128 + sx * 8);
            *(float4*)(rv + 4) = *(float4*)(Vs + kk * 128 + sx * 8 + 4);
#pragma unroll
            for (int i = 0; i < 4; i++) {
                float p = Ss[(sy * 4 + i) * 68 + kk];
#pragma unroll
                for (int j = 0; j < 8; j++)
                    o[i][j] = fmaf(p, rv[j], o[i][j]);
            }
        }
    }

    // finalize: O / l, write ctx [B*S, HID] with col = h*128 + d
#pragma unroll
    for (int i = 0; i < 4; i++) {
        int r = sy * 4 + i;
        float inv_l = 1.0f / s_l[r];
        float vals[8];
#pragma unroll
        for (int j = 0; j < 8; j++) vals[j] = o[i][j] * inv_l;
        size_t off = ((size_t)(b * SEQ + q0 + r)) * HID + h * HD + sx * 8;
        *(float4*)(g_ctx + off)     = *(float4*)(vals);
        *(float4*)(g_ctx + off + 4) = *(float4*)(vals + 4);
    }
}

// ---------------- Output projection: [4096,2048] @ Wout^T + bout -> d_out ----
__global__ __launch_bounds__(256) void out_gemm_kernel(
    const float* __restrict__ W, const float* __restrict__ bias,
    float* __restrict__ out) {
    __shared__ float As[16][132];
    __shared__ float Bs[16][132];
    const int tid = threadIdx.x;
    const int tx = tid & 15, ty = tid >> 4;
    const int bm = blockIdx.y * 128, bn = blockIdx.x * 128;

    float acc[8][8];
#pragma unroll
    for (int i = 0; i < 8; i++)
#pragma unroll
        for (int j = 0; j < 8; j++) acc[i][j] = 0.0f;

    for (int k0 = 0; k0 < HID; k0 += 16) {
#pragma unroll
        for (int it = 0; it < 2; it++) {
            int f = tid * 2 + it;
            int m = f >> 2;
            int kq = (f & 3) << 2;
            float4 a = *(const float4*)(g_ctx + (size_t)(bm + m) * HID + k0 + kq);
            As[kq + 0][m] = a.x; As[kq + 1][m] = a.y;
            As[kq + 2][m] = a.z; As[kq + 3][m] = a.w;
            float4 b = *(const float4*)(W + (size_t)(bn + m) * HID + k0 + kq);
            Bs[kq + 0][m] = b.x; Bs[kq + 1][m] = b.y;
            Bs[kq + 2][m] = b.z; Bs[kq + 3][m] = b.w;
        }
        __syncthreads();
#pragma unroll
        for (int kk = 0; kk < 16; kk++) {
            float ra[8], rb[8];
            *(float4*)(ra)     = *(float4*)&As[kk][ty * 8];
            *(float4*)(ra + 4) = *(float4*)&As[kk][ty * 8 + 4];
            *(float4*)(rb)     = *(float4*)&Bs[kk][tx * 8];
            *(float4*)(rb + 4) = *(float4*)&Bs[kk][tx * 8 + 4];
#pragma unroll
            for (int i = 0; i < 8; i++)
#pragma unroll
                for (int j = 0; j < 8; j++)
                    acc[i][j] = fmaf(ra[i], rb[j], acc[i][j]);
        }
        __syncthreads();
    }

    const int n0 = bn + tx * 8;
    float bv[8];
#pragma unroll
    for (int j = 0; j < 8; j++) bv[j] = bias[n0 + j];
#pragma unroll
    for (int i = 0; i < 8; i++) {
        int gm = bm + ty * 8 + i;
        float vals[8];
#pragma unroll
        for (int j = 0; j < 8; j++) vals[j] = acc[i][j] + bv[j];
        *(float4*)(out + (size_t)gm * HID + n0)     = *(float4*)(vals);
        *(float4*)(out + (size_t)gm * HID + n0 + 4) = *(float4*)(vals + 4);
    }
}

// ---------------- launcher ---------------------------------------------------
extern "C" void kernel_launch(void* const* d_in, const int* in_sizes, int n_in,
                              void* d_out, int out_size) {
    const float* hidden = (const float*)d_in[0];
    const float* mask   = (const float*)d_in[1];
    const float* Wqkv   = (const float*)d_in[2];
    const float* bqkv   = (const float*)d_in[3];
    const float* Wout   = (const float*)d_in[4];
    const float* bout   = (const float*)d_in[5];
    float* out = (float*)d_out;

    rope_table_kernel<<<512, 256>>>();
    qkv_gemm_kernel<<<dim3(48, 32), 256>>>(hidden, Wqkv, bqkv);

    static const size_t attn_smem = 120576;  // 30144 floats
    cudaFuncSetAttribute(attn_kernel,
                         cudaFuncAttributeMaxDynamicSharedMemorySize,
                         (int)attn_smem);
    attn_kernel<<<dim3(32, 16, 2), 256, attn_smem>>>(mask);

    out_gemm_kernel<<<dim3(16, 32), 256>>>(Wout, bout, out);
}

// round 9
// speedup vs baseline: 1.4375x; 1.4375x over previous
#include <cuda_runtime.h>
#include <cuda_bf16.h>
#include <math.h>
#include <stdint.h>

#define BATCH 2
#define SEQ   2048
#define NH    16
#define HD    128
#define HID   2048
#define MROWS 4096   // B*S

// ---------------- scratch (static device globals; no runtime alloc) ----------
__device__ float g_q[(size_t)BATCH * NH * SEQ * HD];
__device__ float g_k[(size_t)BATCH * NH * SEQ * HD];
__device__ float g_v[(size_t)BATCH * NH * SEQ * HD];
__device__ float g_ctx[(size_t)MROWS * HID];
__device__ float g_cos[SEQ * 64];
__device__ float g_sin[SEQ * 64];

// ---------------- helpers ----------------------------------------------------
__device__ __forceinline__ uint32_t smem_u32(const void* p) {
    return (uint32_t)__cvta_generic_to_shared(p);
}
__device__ __forceinline__ void ldm_x4(uint32_t (&r)[4], uint32_t addr) {
    asm volatile("ldmatrix.sync.aligned.m8n8.x4.shared.b16 {%0,%1,%2,%3}, [%4];\n"
        : "=r"(r[0]), "=r"(r[1]), "=r"(r[2]), "=r"(r[3]) : "r"(addr));
}
__device__ __forceinline__ void mma16816(float (&c)[4], const uint32_t (&a)[4],
                                         uint32_t b0, uint32_t b1) {
    asm volatile(
        "mma.sync.aligned.m16n8k16.row.col.f32.bf16.bf16.f32 "
        "{%0,%1,%2,%3}, {%4,%5,%6,%7}, {%8,%9}, {%0,%1,%2,%3};\n"
        : "+f"(c[0]), "+f"(c[1]), "+f"(c[2]), "+f"(c[3])
        : "r"(a[0]), "r"(a[1]), "r"(a[2]), "r"(a[3]), "r"(b0), "r"(b1));
}
__device__ __forceinline__ void split2(float x, unsigned short& h, unsigned short& l) {
    __nv_bfloat16 bh = __float2bfloat16_rn(x);
    h = __bfloat16_as_ushort(bh);
    l = __bfloat16_as_ushort(__float2bfloat16_rn(x - __bfloat162float(bh)));
}
__device__ __forceinline__ uint32_t pk(unsigned short a, unsigned short b) {
    return (uint32_t)a | ((uint32_t)b << 16);
}

// ---------------- RoPE tables ------------------------------------------------
__global__ void rope_table_kernel() {
    int idx = blockIdx.x * 256 + threadIdx.x;
    if (idx >= SEQ * 64) return;
    int s = idx >> 6, i = idx & 63;
    float inv = powf(10000.0f, -(float)(2 * i) / 128.0f);
    float ang = (float)s * inv;
    g_cos[idx] = cosf(ang);
    g_sin[idx] = sinf(ang);
}

// ---------------- split-bf16 tensor GEMM: C = A @ W^T + bias -----------------
// tile 128x128, BK=32, 8 warps (2 along M x 4 along N), warp tile 64x32.
// EPI==0: A = hidden (param), epilogue RoPE q/k + scatter to g_q/g_k/g_v
// EPI==1: A = g_ctx (device symbol, param ignored), epilogue bias + row-major
#define GLD 40   // padded k-stride in bf16 elems (80B rows: 16B-aligned)

template <int EPI>
__global__ __launch_bounds__(256, 1) void mma_gemm_kernel(
    const float* __restrict__ Ain, const float* __restrict__ W,
    const float* __restrict__ bias, float* __restrict__ out) {
    __shared__ unsigned short As_h[128 * GLD], As_l[128 * GLD];
    __shared__ unsigned short Bs_h[128 * GLD], Bs_l[128 * GLD];

    // device-side resolution of the activation source (BUG FIX: never pass a
    // __device__ symbol address from host code)
    const float* __restrict__ A = (EPI == 0) ? Ain : (const float*)g_ctx;

    const int tid = threadIdx.x;
    const int warp = tid >> 5, lane = tid & 31;
    const int g = lane >> 2, tig = lane & 3;
    const int wm = (warp >> 2) * 64, wn = (warp & 3) * 32;
    const int bm = blockIdx.y * 128, bn = blockIdx.x * 128;

    float c[4][4][4];
#pragma unroll
    for (int mt = 0; mt < 4; mt++)
#pragma unroll
        for (int nt = 0; nt < 4; nt++)
#pragma unroll
            for (int q = 0; q < 4; q++) c[mt][nt][q] = 0.0f;

    // ldmatrix base addresses
    uint32_t aH[4], aL[4];
#pragma unroll
    for (int mt = 0; mt < 4; mt++) {
        int r = wm + mt * 16 + (lane & 15);
        int cc = (lane >> 4) << 3;
        aH[mt] = smem_u32(&As_h[r * GLD + cc]);
        aL[mt] = smem_u32(&As_l[r * GLD + cc]);
    }
    uint32_t bH[2], bL[2];
#pragma unroll
    for (int ntp = 0; ntp < 2; ntp++) {
        int r = wn + ntp * 16 + (lane & 7) + ((lane >> 4) << 3);
        int cc = ((lane >> 3) & 1) << 3;
        bH[ntp] = smem_u32(&Bs_h[r * GLD + cc]);
        bL[ntp] = smem_u32(&Bs_l[r * GLD + cc]);
    }

    for (int k0 = 0; k0 < HID; k0 += 32) {
#pragma unroll
        for (int i = 0; i < 4; i++) {
            int idx = tid + i * 256;             // 0..1023
            int r = idx >> 3, kq = (idx & 7) << 2;
            float4 av = *(const float4*)(A + (size_t)(bm + r) * HID + k0 + kq);
            float4 wv = *(const float4*)(W + (size_t)(bn + r) * HID + k0 + kq);
            unsigned short h0, h1, h2, h3, l0, l1, l2, l3;
            split2(av.x, h0, l0); split2(av.y, h1, l1);
            split2(av.z, h2, l2); split2(av.w, h3, l3);
            *(uint2*)&As_h[r * GLD + kq] = make_uint2(pk(h0, h1), pk(h2, h3));
            *(uint2*)&As_l[r * GLD + kq] = make_uint2(pk(l0, l1), pk(l2, l3));
            split2(wv.x, h0, l0); split2(wv.y, h1, l1);
            split2(wv.z, h2, l2); split2(wv.w, h3, l3);
            *(uint2*)&Bs_h[r * GLD + kq] = make_uint2(pk(h0, h1), pk(h2, h3));
            *(uint2*)&Bs_l[r * GLD + kq] = make_uint2(pk(l0, l1), pk(l2, l3));
        }
        __syncthreads();

#pragma unroll
        for (int ks = 0; ks < 2; ks++) {
            const uint32_t ko = ks * 32;   // 16 bf16 = 32 bytes
            uint32_t Ah[4][4], Al[4][4];
#pragma unroll
            for (int mt = 0; mt < 4; mt++) {
                ldm_x4(Ah[mt], aH[mt] + ko);
                ldm_x4(Al[mt], aL[mt] + ko);
            }
            uint32_t Bh[4][2], Bl[4][2];
#pragma unroll
            for (int ntp = 0; ntp < 2; ntp++) {
                uint32_t t[4];
                ldm_x4(t, bH[ntp] + ko);
                Bh[2 * ntp][0] = t[0]; Bh[2 * ntp][1] = t[1];
                Bh[2 * ntp + 1][0] = t[2]; Bh[2 * ntp + 1][1] = t[3];
                ldm_x4(t, bL[ntp] + ko);
                Bl[2 * ntp][0] = t[0]; Bl[2 * ntp][1] = t[1];
                Bl[2 * ntp + 1][0] = t[2]; Bl[2 * ntp + 1][1] = t[3];
            }
#pragma unroll
            for (int mt = 0; mt < 4; mt++)
#pragma unroll
                for (int nt = 0; nt < 4; nt++) {
                    mma16816(c[mt][nt], Ah[mt], Bh[nt][0], Bh[nt][1]);
                    mma16816(c[mt][nt], Ah[mt], Bl[nt][0], Bl[nt][1]);
                    mma16816(c[mt][nt], Al[mt], Bh[nt][0], Bh[nt][1]);
                }
        }
        __syncthreads();
    }

    // epilogue
#pragma unroll
    for (int nt = 0; nt < 4; nt++) {
        const int n0 = bn + wn + nt * 8 + 2 * tig;
        const float bv0 = bias[n0], bv1 = bias[n0 + 1];
#pragma unroll
        for (int mt = 0; mt < 4; mt++) {
#pragma unroll
            for (int half = 0; half < 2; half++) {
                int gm = bm + wm + mt * 16 + g + half * 8;
                float v0 = c[mt][nt][half * 2 + 0] + bv0;
                float v1 = c[mt][nt][half * 2 + 1] + bv1;
                if (EPI == 0) {
                    int seg = n0 >> 11;
                    int h = (n0 >> 7) & 15;
                    int d0 = n0 & 127;
                    int b = gm >> 11, s = gm & 2047;
                    float* dst;
                    if (seg < 2) {
                        float cc = g_cos[s * 64 + (d0 >> 1)];
                        float ss = g_sin[s * 64 + (d0 >> 1)];
                        float e = v0, o = v1;
                        v0 = e * cc - o * ss;
                        v1 = e * ss + o * cc;
                        dst = (seg == 0) ? g_q : g_k;
                    } else {
                        dst = g_v;
                    }
                    size_t off = (((size_t)b * NH + h) * SEQ + s) * HD + d0;
                    *(float2*)(dst + off) = make_float2(v0, v1);
                } else {
                    *(float2*)(out + (size_t)gm * HID + n0) = make_float2(v0, v1);
                }
            }
        }
    }
}

// ---------------- flash attention with split-bf16 tensor MMA -----------------
// Br=64, Bc=64, D=128. 256 threads (8 warps).
// QK phase: warps 4(m16) x 2(n32).  PV/O phase: warps 2(m32) x 4(n32).
#define QLD 136   // Q/K padded k-stride (272B rows)
#define VLD 72    // V^T / P padded k-stride (144B rows)

__global__ __launch_bounds__(256, 1) void attn_mma_kernel(const float* __restrict__ mask) {
    extern __shared__ unsigned char smraw[];
    unsigned short* Qh = (unsigned short*)smraw;          // [64][136]
    unsigned short* Ql = Qh + 64 * QLD;
    unsigned short* Kh = Ql + 64 * QLD;                   // [64][136]
    unsigned short* Kl = Kh + 64 * QLD;
    unsigned short* Vh = Kl + 64 * QLD;                   // [128][72]  (d-major, s contig)
    unsigned short* Vl = Vh + 128 * VLD;
    unsigned short* Ph = Vl + 128 * VLD;                  // [64][72]
    unsigned short* Pl = Ph + 64 * VLD;
    float* s_m  = (float*)(Pl + 64 * VLD);                // [64]
    float* s_l  = s_m + 64;                               // [64]
    float* s_al = s_l + 64;                               // [64]
    float* pmax = s_al + 64;                              // [2][64]
    float* psum = pmax + 128;                             // [2][64]

    const int tid = threadIdx.x;
    const int warp = tid >> 5, lane = tid & 31;
    const int g = lane >> 2, tig = lane & 3;
    const int q0 = blockIdx.x * 64;
    const int h = blockIdx.y, b = blockIdx.z;
    const size_t head_base = ((size_t)b * NH + h) * SEQ * HD;
    const float scale = 0.08838834764831845f;

    // QK phase mapping
    const int qm = (warp >> 1) * 16;   // row tile within 64
    const int nh = (warp & 1) * 32;    // col half
    // PV/O phase mapping
    const int om = (warp >> 2) * 32;   // 2 m-tiles of 16
    const int on = (warp & 3) * 32;    // 4 n8-tiles

    // load Q once (split into hi/lo bf16)
#pragma unroll
    for (int i = 0; i < 8; i++) {
        int idx = tid + i * 256;           // 0..2047
        int r = idx >> 5, kq = (idx & 31) << 2;
        float4 qv = *(const float4*)(g_q + head_base + (size_t)(q0 + r) * HD + kq);
        unsigned short h0, h1, h2, h3, l0, l1, l2, l3;
        split2(qv.x, h0, l0); split2(qv.y, h1, l1);
        split2(qv.z, h2, l2); split2(qv.w, h3, l3);
        *(uint2*)&Qh[r * QLD + kq] = make_uint2(pk(h0, h1), pk(h2, h3));
        *(uint2*)&Ql[r * QLD + kq] = make_uint2(pk(l0, l1), pk(l2, l3));
    }
    if (tid < 64) { s_m[tid] = -INFINITY; s_l[tid] = 0.0f; }

    // ldmatrix bases
    uint32_t qbH = smem_u32(&Qh[(qm + (lane & 15)) * QLD + ((lane >> 4) << 3)]);
    uint32_t qbL = smem_u32(&Ql[(qm + (lane & 15)) * QLD + ((lane >> 4) << 3)]);
    uint32_t kbH[2], kbL[2], vbH[2], vbL[2], pbH[2], pbL[2];
#pragma unroll
    for (int ntp = 0; ntp < 2; ntp++) {
        int r = nh + ntp * 16 + (lane & 7) + ((lane >> 4) << 3);
        int cc = ((lane >> 3) & 1) << 3;
        kbH[ntp] = smem_u32(&Kh[r * QLD + cc]);
        kbL[ntp] = smem_u32(&Kl[r * QLD + cc]);
        int rv = on + ntp * 16 + (lane & 7) + ((lane >> 4) << 3);
        vbH[ntp] = smem_u32(&Vh[rv * VLD + cc]);
        vbL[ntp] = smem_u32(&Vl[rv * VLD + cc]);
    }
#pragma unroll
    for (int mt = 0; mt < 2; mt++) {
        int r = om + mt * 16 + (lane & 15);
        int cc = (lane >> 4) << 3;
        pbH[mt] = smem_u32(&Ph[r * VLD + cc]);
        pbL[mt] = smem_u32(&Pl[r * VLD + cc]);
    }

    float co[2][4][4];
#pragma unroll
    for (int mt = 0; mt < 2; mt++)
#pragma unroll
        for (int nt = 0; nt < 4; nt++)
#pragma unroll
            for (int q = 0; q < 4; q++) co[mt][nt][q] = 0.0f;

    const float* mrow = mask + (size_t)b * SEQ;

    for (int k0 = 0; k0 < SEQ; k0 += 64) {
        __syncthreads();   // prior PV done before overwriting K/V
        // load K (split)
#pragma unroll
        for (int i = 0; i < 8; i++) {
            int idx = tid + i * 256;
            int r = idx >> 5, kq = (idx & 31) << 2;
            float4 kv = *(const float4*)(g_k + head_base + (size_t)(k0 + r) * HD + kq);
            unsigned short h0, h1, h2, h3, l0, l1, l2, l3;
            split2(kv.x, h0, l0); split2(kv.y, h1, l1);
            split2(kv.z, h2, l2); split2(kv.w, h3, l3);
            *(uint2*)&Kh[r * QLD + kq] = make_uint2(pk(h0, h1), pk(h2, h3));
            *(uint2*)&Kl[r * QLD + kq] = make_uint2(pk(l0, l1), pk(l2, l3));
        }
        // load V transposed: Vh[d][s_local]
#pragma unroll
        for (int i = 0; i < 8; i++) {
            int idx = tid + i * 256;           // 0..2047
            int d = idx & 127, sg = idx >> 7;  // sg 0..15
            int s0 = sg * 4;
            unsigned short hh[4], ll[4];
#pragma unroll
            for (int j = 0; j < 4; j++) {
                float v = g_v[head_base + (size_t)(k0 + s0 + j) * HD + d];
                split2(v, hh[j], ll[j]);
            }
            *(uint2*)&Vh[d * VLD + s0] = make_uint2(pk(hh[0], hh[1]), pk(hh[2], hh[3]));
            *(uint2*)&Vl[d * VLD + s0] = make_uint2(pk(ll[0], ll[1]), pk(ll[2], ll[3]));
        }
        __syncthreads();

        // ---- S = Q @ K^T (warp: 16 rows x 32 cols, k=128) ----
        float cs[4][4];
#pragma unroll
        for (int nt = 0; nt < 4; nt++)
#pragma unroll
            for (int q = 0; q < 4; q++) cs[nt][q] = 0.0f;
#pragma unroll
        for (int k16 = 0; k16 < 8; k16++) {
            const uint32_t ko = k16 * 32;
            uint32_t Ahf[4], Alf[4];
            ldm_x4(Ahf, qbH + ko);
            ldm_x4(Alf, qbL + ko);
            uint32_t Bh[4][2], Bl[4][2];
#pragma unroll
            for (int ntp = 0; ntp < 2; ntp++) {
                uint32_t t[4];
                ldm_x4(t, kbH[ntp] + ko);
                Bh[2 * ntp][0] = t[0]; Bh[2 * ntp][1] = t[1];
                Bh[2 * ntp + 1][0] = t[2]; Bh[2 * ntp + 1][1] = t[3];
                ldm_x4(t, kbL[ntp] + ko);
                Bl[2 * ntp][0] = t[0]; Bl[2 * ntp][1] = t[1];
                Bl[2 * ntp + 1][0] = t[2]; Bl[2 * ntp + 1][1] = t[3];
            }
#pragma unroll
            for (int nt = 0; nt < 4; nt++) {
                mma16816(cs[nt], Ahf, Bh[nt][0], Bh[nt][1]);
                mma16816(cs[nt], Ahf, Bl[nt][0], Bl[nt][1]);
                mma16816(cs[nt], Alf, Bh[nt][0], Bh[nt][1]);
            }
        }

        // scale + mask + partial row max
        float m0 = -INFINITY, m1 = -INFINITY;
#pragma unroll
        for (int nt = 0; nt < 4; nt++) {
            int cb = nh + nt * 8 + 2 * tig;
            float mk0 = mrow[k0 + cb], mk1 = mrow[k0 + cb + 1];
            cs[nt][0] = cs[nt][0] * scale + mk0;
            cs[nt][1] = cs[nt][1] * scale + mk1;
            cs[nt][2] = cs[nt][2] * scale + mk0;
            cs[nt][3] = cs[nt][3] * scale + mk1;
            m0 = fmaxf(m0, fmaxf(cs[nt][0], cs[nt][1]));
            m1 = fmaxf(m1, fmaxf(cs[nt][2], cs[nt][3]));
        }
        m0 = fmaxf(m0, __shfl_xor_sync(0xffffffffu, m0, 1));
        m0 = fmaxf(m0, __shfl_xor_sync(0xffffffffu, m0, 2));
        m1 = fmaxf(m1, __shfl_xor_sync(0xffffffffu, m1, 1));
        m1 = fmaxf(m1, __shfl_xor_sync(0xffffffffu, m1, 2));
        if (tig == 0) {
            pmax[(warp & 1) * 64 + qm + g] = m0;
            pmax[(warp & 1) * 64 + qm + 8 + g] = m1;
        }
        __syncthreads();
        if (tid < 64) {
            float mo = s_m[tid];
            float mn = fmaxf(mo, fmaxf(pmax[tid], pmax[64 + tid]));
            s_al[tid] = __expf(mo - mn);
            s_m[tid] = mn;
        }
        __syncthreads();

        // exp, write split P, partial row sums
        {
            float mn0 = s_m[qm + g], mn1 = s_m[qm + 8 + g];
            float sum0 = 0.0f, sum1 = 0.0f;
#pragma unroll
            for (int nt = 0; nt < 4; nt++) {
                int col = nh + nt * 8 + 2 * tig;
                float p00 = __expf(cs[nt][0] - mn0);
                float p01 = __expf(cs[nt][1] - mn0);
                float p10 = __expf(cs[nt][2] - mn1);
                float p11 = __expf(cs[nt][3] - mn1);
                sum0 += p00 + p01;
                sum1 += p10 + p11;
                unsigned short h0, h1, l0, l1;
                split2(p00, h0, l0); split2(p01, h1, l1);
                *(uint32_t*)&Ph[(qm + g) * VLD + col] = pk(h0, h1);
                *(uint32_t*)&Pl[(qm + g) * VLD + col] = pk(l0, l1);
                split2(p10, h0, l0); split2(p11, h1, l1);
                *(uint32_t*)&Ph[(qm + 8 + g) * VLD + col] = pk(h0, h1);
                *(uint32_t*)&Pl[(qm + 8 + g) * VLD + col] = pk(l0, l1);
            }
            sum0 += __shfl_xor_sync(0xffffffffu, sum0, 1);
            sum0 += __shfl_xor_sync(0xffffffffu, sum0, 2);
            sum1 += __shfl_xor_sync(0xffffffffu, sum1, 1);
            sum1 += __shfl_xor_sync(0xffffffffu, sum1, 2);
            if (tig == 0) {
                psum[(warp & 1) * 64 + qm + g] = sum0;
                psum[(warp & 1) * 64 + qm + 8 + g] = sum1;
            }
        }
        __syncthreads();
        if (tid < 64)
            s_l[tid] = s_l[tid] * s_al[tid] + psum[tid] + psum[64 + tid];

        // ---- rescale O then O += P @ V (warp: 32 rows x 32 cols, k=64) ----
#pragma unroll
        for (int mt = 0; mt < 2; mt++) {
            float a0 = s_al[om + mt * 16 + g];
            float a1 = s_al[om + mt * 16 + 8 + g];
#pragma unroll
            for (int nt = 0; nt < 4; nt++) {
                co[mt][nt][0] *= a0; co[mt][nt][1] *= a0;
                co[mt][nt][2] *= a1; co[mt][nt][3] *= a1;
            }
        }
#pragma unroll
        for (int k16 = 0; k16 < 4; k16++) {
            const uint32_t ko = k16 * 32;
            uint32_t Bh[4][2], Bl[4][2];
#pragma unroll
            for (int ntp = 0; ntp < 2; ntp++) {
                uint32_t t[4];
                ldm_x4(t, vbH[ntp] + ko);
                Bh[2 * ntp][0] = t[0]; Bh[2 * ntp][1] = t[1];
                Bh[2 * ntp + 1][0] = t[2]; Bh[2 * ntp + 1][1] = t[3];
                ldm_x4(t, vbL[ntp] + ko);
                Bl[2 * ntp][0] = t[0]; Bl[2 * ntp][1] = t[1];
                Bl[2 * ntp + 1][0] = t[2]; Bl[2 * ntp + 1][1] = t[3];
            }
#pragma unroll
            for (int mt = 0; mt < 2; mt++) {
                uint32_t Ahf[4], Alf[4];
                ldm_x4(Ahf, pbH[mt] + ko);
                ldm_x4(Alf, pbL[mt] + ko);
#pragma unroll
                for (int nt = 0; nt < 4; nt++) {
                    mma16816(co[mt][nt], Ahf, Bh[nt][0], Bh[nt][1]);
                    mma16816(co[mt][nt], Ahf, Bl[nt][0], Bl[nt][1]);
                    mma16816(co[mt][nt], Alf, Bh[nt][0], Bh[nt][1]);
                }
            }
        }
    }

    __syncthreads();   // s_l final values visible to all
    // finalize: O / l -> g_ctx [B*S, HID], cols h*128 + d
#pragma unroll
    for (int mt = 0; mt < 2; mt++) {
        int r0 = om + mt * 16 + g;
        int r1 = r0 + 8;
        float inv0 = 1.0f / s_l[r0];
        float inv1 = 1.0f / s_l[r1];
#pragma unroll
        for (int nt = 0; nt < 4; nt++) {
            int col = h * HD + on + nt * 8 + 2 * tig;
            size_t base0 = (size_t)(b * SEQ + q0 + r0) * HID + col;
            size_t base1 = (size_t)(b * SEQ + q0 + r1) * HID + col;
            *(float2*)(g_ctx + base0) =
                make_float2(co[mt][nt][0] * inv0, co[mt][nt][1] * inv0);
            *(float2*)(g_ctx + base1) =
                make_float2(co[mt][nt][2] * inv1, co[mt][nt][3] * inv1);
        }
    }
}

// ---------------- launcher ---------------------------------------------------
extern "C" void kernel_launch(void* const* d_in, const int* in_sizes, int n_in,
                              void* d_out, int out_size) {
    const float* hidden = (const float*)d_in[0];
    const float* mask   = (const float*)d_in[1];
    const float* Wqkv   = (const float*)d_in[2];
    const float* bqkv   = (const float*)d_in[3];
    const float* Wout   = (const float*)d_in[4];
    const float* bout   = (const float*)d_in[5];
    float* out = (float*)d_out;

    rope_table_kernel<<<512, 256>>>();

    mma_gemm_kernel<0><<<dim3(48, 32), 256>>>(hidden, Wqkv, bqkv, nullptr);

    const int attn_smem = 126720;
    cudaFuncSetAttribute(attn_mma_kernel,
                         cudaFuncAttributeMaxDynamicSharedMemorySize, attn_smem);
    attn_mma_kernel<<<dim3(SEQ / 64, NH, BATCH), 256, attn_smem>>>(mask);

    mma_gemm_kernel<1><<<dim3(16, 32), 256>>>(nullptr, Wout, bout, out);
}

// round 11
// speedup vs baseline: 2.9505x; 2.0526x over previous
#include <cuda_runtime.h>
#include <cuda_bf16.h>
#include <math.h>
#include <stdint.h>

#define BATCH 2
#define SEQ   2048
#define NH    16
#define HD    128
#define HID   2048
#define NQKV  6144
#define MROWS 4096   // B*S
#define QKV_ELEMS ((size_t)BATCH * NH * SEQ * HD)

// ---------------- scratch (static device globals; no runtime alloc) ----------
__device__ unsigned short g_hid_h[(size_t)MROWS * HID], g_hid_l[(size_t)MROWS * HID];
__device__ unsigned short g_wqkv_h[(size_t)NQKV * HID], g_wqkv_l[(size_t)NQKV * HID];
__device__ unsigned short g_wout_h[(size_t)HID * HID], g_wout_l[(size_t)HID * HID];
__device__ unsigned short g_q_h[QKV_ELEMS], g_q_l[QKV_ELEMS];
__device__ unsigned short g_k_h[QKV_ELEMS], g_k_l[QKV_ELEMS];
__device__ unsigned short g_v_h[QKV_ELEMS], g_v_l[QKV_ELEMS];
__device__ unsigned short g_ctx_h[(size_t)MROWS * HID], g_ctx_l[(size_t)MROWS * HID];
__device__ float g_cos[SEQ * 64], g_sin[SEQ * 64];

// ---------------- helpers ----------------------------------------------------
__device__ __forceinline__ uint32_t smem_u32(const void* p) {
    return (uint32_t)__cvta_generic_to_shared(p);
}
__device__ __forceinline__ void ldm_x4(uint32_t (&r)[4], uint32_t addr) {
    asm volatile("ldmatrix.sync.aligned.m8n8.x4.shared.b16 {%0,%1,%2,%3}, [%4];\n"
        : "=r"(r[0]), "=r"(r[1]), "=r"(r[2]), "=r"(r[3]) : "r"(addr));
}
__device__ __forceinline__ void ldm_x4_t(uint32_t (&r)[4], uint32_t addr) {
    asm volatile("ldmatrix.sync.aligned.m8n8.x4.trans.shared.b16 {%0,%1,%2,%3}, [%4];\n"
        : "=r"(r[0]), "=r"(r[1]), "=r"(r[2]), "=r"(r[3]) : "r"(addr));
}
__device__ __forceinline__ void mma16816(float (&c)[4], const uint32_t (&a)[4],
                                         uint32_t b0, uint32_t b1) {
    asm volatile(
        "mma.sync.aligned.m16n8k16.row.col.f32.bf16.bf16.f32 "
        "{%0,%1,%2,%3}, {%4,%5,%6,%7}, {%8,%9}, {%0,%1,%2,%3};\n"
        : "+f"(c[0]), "+f"(c[1]), "+f"(c[2]), "+f"(c[3])
        : "r"(a[0]), "r"(a[1]), "r"(a[2]), "r"(a[3]), "r"(b0), "r"(b1));
}
__device__ __forceinline__ void split2(float x, unsigned short& h, unsigned short& l) {
    __nv_bfloat16 bh = __float2bfloat16_rn(x);
    h = __bfloat16_as_ushort(bh);
    l = __bfloat16_as_ushort(__float2bfloat16_rn(x - __bfloat162float(bh)));
}
__device__ __forceinline__ uint32_t pk(unsigned short a, unsigned short b) {
    return (uint32_t)a | ((uint32_t)b << 16);
}
__device__ __forceinline__ void cp16(uint32_t s, const void* g) {
    asm volatile("cp.async.cg.shared.global [%0], [%1], 16;\n" :: "r"(s), "l"(g));
}
__device__ __forceinline__ void cp_commit() {
    asm volatile("cp.async.commit_group;\n");
}
template <int N> __device__ __forceinline__ void cp_wait() {
    asm volatile("cp.async.wait_group %0;\n" :: "n"(N));
}

// ---------------- one-time fp32 -> bf16 hi/lo split --------------------------
__global__ void split_kernel(const float* __restrict__ src, int sel, int n4) {
    int i = blockIdx.x * 256 + threadIdx.x;
    if (i >= n4) return;
    unsigned short *dh, *dl;
    if (sel == 0)      { dh = g_hid_h;  dl = g_hid_l;  }
    else if (sel == 1) { dh = g_wqkv_h; dl = g_wqkv_l; }
    else               { dh = g_wout_h; dl = g_wout_l; }
    float4 v = ((const float4*)src)[i];
    unsigned short h0, h1, h2, h3, l0, l1, l2, l3;
    split2(v.x, h0, l0); split2(v.y, h1, l1);
    split2(v.z, h2, l2); split2(v.w, h3, l3);
    ((uint2*)dh)[i] = make_uint2(pk(h0, h1), pk(h2, h3));
    ((uint2*)dl)[i] = make_uint2(pk(l0, l1), pk(l2, l3));
}

// ---------------- RoPE tables ------------------------------------------------
__global__ void rope_table_kernel() {
    int idx = blockIdx.x * 256 + threadIdx.x;
    if (idx >= SEQ * 64) return;
    int s = idx >> 6, i = idx & 63;
    float inv = powf(10000.0f, -(float)(2 * i) / 128.0f);
    float ang = (float)s * inv;
    g_cos[idx] = cosf(ang);
    g_sin[idx] = sinf(ang);
}

// ---------------- split-bf16 tensor GEMM, cp.async double-buffered -----------
// tile 128x128, BK=32, 8 warps (2M x 4N), warp tile 64x32.
// EPI==0: A=g_hid, B=g_wqkv, epilogue RoPE + scatter split bf16 q/k/v
// EPI==1: A=g_ctx, B=g_wout, epilogue bias + fp32 row-major out
#define GLD 40   // padded k-stride in bf16 elems (80B rows)

template <int EPI>
__global__ __launch_bounds__(256, 1) void mma_gemm_kernel(
    const float* __restrict__ bias, float* __restrict__ out) {
    extern __shared__ unsigned short sm[];
    unsigned short* sAh = sm;                       // [2][128*GLD]
    unsigned short* sAl = sAh + 2 * 128 * GLD;
    unsigned short* sBh = sAl + 2 * 128 * GLD;
    unsigned short* sBl = sBh + 2 * 128 * GLD;

    const unsigned short *Ah_g, *Al_g, *Bh_g, *Bl_g;
    if (EPI == 0) { Ah_g = g_hid_h; Al_g = g_hid_l; Bh_g = g_wqkv_h; Bl_g = g_wqkv_l; }
    else          { Ah_g = g_ctx_h; Al_g = g_ctx_l; Bh_g = g_wout_h; Bl_g = g_wout_l; }

    const int tid = threadIdx.x;
    const int warp = tid >> 5, lane = tid & 31;
    const int g = lane >> 2, tig = lane & 3;
    const int wm = (warp >> 2) * 64, wn = (warp & 3) * 32;
    const int bm = blockIdx.y * 128, bn = blockIdx.x * 128;

    float c[4][4][4];
#pragma unroll
    for (int mt = 0; mt < 4; mt++)
#pragma unroll
        for (int nt = 0; nt < 4; nt++)
#pragma unroll
            for (int q = 0; q < 4; q++) c[mt][nt][q] = 0.0f;

    // ldmatrix base addresses (stage 0)
    uint32_t aH[4], aL[4];
#pragma unroll
    for (int mt = 0; mt < 4; mt++) {
        int r = wm + mt * 16 + (lane & 15);
        int cc = (lane >> 4) << 3;
        aH[mt] = smem_u32(&sAh[r * GLD + cc]);
        aL[mt] = smem_u32(&sAl[r * GLD + cc]);
    }
    uint32_t bH[2], bL[2];
#pragma unroll
    for (int ntp = 0; ntp < 2; ntp++) {
        int r = wn + ntp * 16 + (lane & 7) + ((lane >> 4) << 3);
        int cc = ((lane >> 3) & 1) << 3;
        bH[ntp] = smem_u32(&sBh[r * GLD + cc]);
        bL[ntp] = smem_u32(&sBl[r * GLD + cc]);
    }

    auto load_stage = [&](int st, int k0) {
        int off = st * 128 * GLD;
#pragma unroll
        for (int i = 0; i < 2; i++) {
            int cch = tid + i * 256;               // 0..511
            int r = cch >> 2, col = (cch & 3) << 3;
            size_t ga = (size_t)(bm + r) * HID + k0 + col;
            size_t gb = (size_t)(bn + r) * HID + k0 + col;
            int so = off + r * GLD + col;
            cp16(smem_u32(&sAh[so]), Ah_g + ga);
            cp16(smem_u32(&sAl[so]), Al_g + ga);
            cp16(smem_u32(&sBh[so]), Bh_g + gb);
            cp16(smem_u32(&sBl[so]), Bl_g + gb);
        }
    };

    load_stage(0, 0);
    cp_commit();

#pragma unroll 1
    for (int kt = 0; kt < HID / 32; kt++) {
        if (kt + 1 < HID / 32) load_stage((kt + 1) & 1, (kt + 1) * 32);
        cp_commit();
        cp_wait<1>();
        __syncthreads();

        const uint32_t stb = (uint32_t)((kt & 1) * 128 * GLD * 2);
#pragma unroll
        for (int ks = 0; ks < 2; ks++) {
            const uint32_t ko = stb + ks * 32;     // 16 bf16 = 32 bytes
            uint32_t Ah[4][4], Al[4][4];
#pragma unroll
            for (int mt = 0; mt < 4; mt++) {
                ldm_x4(Ah[mt], aH[mt] + ko);
                ldm_x4(Al[mt], aL[mt] + ko);
            }
            uint32_t Bh[4][2], Bl[4][2];
#pragma unroll
            for (int ntp = 0; ntp < 2; ntp++) {
                uint32_t t[4];
                ldm_x4(t, bH[ntp] + ko);
                Bh[2 * ntp][0] = t[0]; Bh[2 * ntp][1] = t[1];
                Bh[2 * ntp + 1][0] = t[2]; Bh[2 * ntp + 1][1] = t[3];
                ldm_x4(t, bL[ntp] + ko);
                Bl[2 * ntp][0] = t[0]; Bl[2 * ntp][1] = t[1];
                Bl[2 * ntp + 1][0] = t[2]; Bl[2 * ntp + 1][1] = t[3];
            }
#pragma unroll
            for (int mt = 0; mt < 4; mt++)
#pragma unroll
                for (int nt = 0; nt < 4; nt++) {
                    mma16816(c[mt][nt], Ah[mt], Bh[nt][0], Bh[nt][1]);
                    mma16816(c[mt][nt], Ah[mt], Bl[nt][0], Bl[nt][1]);
                    mma16816(c[mt][nt], Al[mt], Bh[nt][0], Bh[nt][1]);
                }
        }
        __syncthreads();
    }

    // epilogue
#pragma unroll
    for (int nt = 0; nt < 4; nt++) {
        const int n0 = bn + wn + nt * 8 + 2 * tig;
        const float bv0 = bias[n0], bv1 = bias[n0 + 1];
#pragma unroll
        for (int mt = 0; mt < 4; mt++) {
#pragma unroll
            for (int half = 0; half < 2; half++) {
                int gm = bm + wm + mt * 16 + g + half * 8;
                float v0 = c[mt][nt][half * 2 + 0] + bv0;
                float v1 = c[mt][nt][half * 2 + 1] + bv1;
                if (EPI == 0) {
                    int seg = n0 >> 11;
                    int h = (n0 >> 7) & 15;
                    int d0 = n0 & 127;
                    int b = gm >> 11, s = gm & 2047;
                    unsigned short *dh, *dl;
                    if (seg < 2) {
                        float cc = g_cos[s * 64 + (d0 >> 1)];
                        float ss = g_sin[s * 64 + (d0 >> 1)];
                        float e = v0, o = v1;
                        v0 = e * cc - o * ss;
                        v1 = e * ss + o * cc;
                        if (seg == 0) { dh = g_q_h; dl = g_q_l; }
                        else          { dh = g_k_h; dl = g_k_l; }
                    } else { dh = g_v_h; dl = g_v_l; }
                    size_t off = (((size_t)b * NH + h) * SEQ + s) * HD + d0;
                    unsigned short h0, h1, l0, l1;
                    split2(v0, h0, l0); split2(v1, h1, l1);
                    *(uint32_t*)&dh[off] = pk(h0, h1);
                    *(uint32_t*)&dl[off] = pk(l0, l1);
                } else {
                    *(float2*)(out + (size_t)gm * HID + n0) = make_float2(v0, v1);
                }
            }
        }
    }
}

// ---------------- flash attention, cp.async + split-bf16 MMA -----------------
// Br=64, Bc=64, D=128. 256 threads (8 warps). K/V double-buffered.
#define QLD 136   // Q/K/V padded stride (272B rows)
#define VLD 72    // P padded k-stride (144B rows)
#define KV_STG (64 * QLD * 2)       // bytes per stage per array
#define K16_STRIDE (16 * QLD * 2)   // bytes per 16 V-rows
// smem: 10 * 64*QLD shorts (Q hi/lo + 2-stage K hi/lo + 2-stage V hi/lo)
//     +  2 * 64*VLD shorts (P hi/lo) + 448 floats
#define ATTN_SMEM ((10 * 64 * QLD + 2 * 64 * VLD) * 2 + 448 * 4)   // 194304 B

__global__ __launch_bounds__(256, 1) void attn_mma_kernel(const float* __restrict__ mask) {
    extern __shared__ unsigned short asm_[];
    unsigned short* sQh = asm_;                     // [64][136]
    unsigned short* sQl = sQh + 64 * QLD;
    unsigned short* sKh = sQl + 64 * QLD;           // [2][64][136]
    unsigned short* sKl = sKh + 2 * 64 * QLD;
    unsigned short* sVh = sKl + 2 * 64 * QLD;       // [2][64][136]  natural [s][d]
    unsigned short* sVl = sVh + 2 * 64 * QLD;
    unsigned short* sPh = sVl + 2 * 64 * QLD;       // [64][72]
    unsigned short* sPl = sPh + 64 * VLD;
    float* s_m  = (float*)(sPl + 64 * VLD);         // [64]
    float* s_l  = s_m + 64;
    float* s_al = s_l + 64;
    float* pmax = s_al + 64;                        // [2][64]
    float* psum = pmax + 128;                       // [2][64]

    const int tid = threadIdx.x;
    const int warp = tid >> 5, lane = tid & 31;
    const int g = lane >> 2, tig = lane & 3;
    const int q0 = blockIdx.x * 64;
    const int h = blockIdx.y, b = blockIdx.z;
    const size_t head_base = ((size_t)b * NH + h) * SEQ * HD;
    const float scale = 0.08838834764831845f;

    // QK phase mapping: 4 warps along M(16), 2 along N(32)
    const int qm = (warp >> 1) * 16;
    const int nh = (warp & 1) * 32;
    // PV phase mapping: 2 warps along M(32), 4 along N(32)
    const int om = (warp >> 2) * 32;
    const int on = (warp & 3) * 32;

    // Q load (group 0)
#pragma unroll
    for (int i = 0; i < 4; i++) {
        int cch = tid + i * 256;                    // 0..1023
        int r = cch >> 4, col = (cch & 15) << 3;
        size_t ga = head_base + (size_t)(q0 + r) * HD + col;
        cp16(smem_u32(&sQh[r * QLD + col]), g_q_h + ga);
        cp16(smem_u32(&sQl[r * QLD + col]), g_q_l + ga);
    }
    cp_commit();

    auto load_kv = [&](int st, int k0) {
        int off = st * 64 * QLD;
#pragma unroll
        for (int i = 0; i < 4; i++) {
            int cch = tid + i * 256;
            int r = cch >> 4, col = (cch & 15) << 3;
            size_t ga = head_base + (size_t)(k0 + r) * HD + col;
            int so = off + r * QLD + col;
            cp16(smem_u32(&sKh[so]), g_k_h + ga);
            cp16(smem_u32(&sKl[so]), g_k_l + ga);
            cp16(smem_u32(&sVh[so]), g_v_h + ga);
            cp16(smem_u32(&sVl[so]), g_v_l + ga);
        }
    };
    load_kv(0, 0);
    cp_commit();

    if (tid < 64) { s_m[tid] = -INFINITY; s_l[tid] = 0.0f; }

    // ldmatrix bases (stage 0)
    uint32_t qbH = smem_u32(&sQh[(qm + (lane & 15)) * QLD + ((lane >> 4) << 3)]);
    uint32_t qbL = smem_u32(&sQl[(qm + (lane & 15)) * QLD + ((lane >> 4) << 3)]);
    uint32_t kbH[2], kbL[2], vbH[2], vbL[2], pbH[2], pbL[2];
#pragma unroll
    for (int ntp = 0; ntp < 2; ntp++) {
        int r = nh + ntp * 16 + (lane & 7) + ((lane >> 4) << 3);
        int cc = ((lane >> 3) & 1) << 3;
        kbH[ntp] = smem_u32(&sKh[r * QLD + cc]);
        kbL[ntp] = smem_u32(&sKl[r * QLD + cc]);
        // V: trans ldmatrix over natural [s][d]: rows = k(s), cols = n(d)
        int vr = (lane & 15);                       // k row within 16
        int vc = on + ntp * 16 + ((lane >> 4) << 3);
        vbH[ntp] = smem_u32(&sVh[vr * QLD + vc]);
        vbL[ntp] = smem_u32(&sVl[vr * QLD + vc]);
    }
#pragma unroll
    for (int mt = 0; mt < 2; mt++) {
        int r = om + mt * 16 + (lane & 15);
        int cc = (lane >> 4) << 3;
        pbH[mt] = smem_u32(&sPh[r * VLD + cc]);
        pbL[mt] = smem_u32(&sPl[r * VLD + cc]);
    }

    float co[2][4][4];
#pragma unroll
    for (int mt = 0; mt < 2; mt++)
#pragma unroll
        for (int nt = 0; nt < 4; nt++)
#pragma unroll
            for (int q = 0; q < 4; q++) co[mt][nt][q] = 0.0f;

    const float* mrow = mask + (size_t)b * SEQ;

#pragma unroll 1
    for (int kt = 0; kt < SEQ / 64; kt++) {
        const int k0 = kt * 64;
        if (kt + 1 < SEQ / 64) load_kv((kt + 1) & 1, (kt + 1) * 64);
        cp_commit();
        cp_wait<1>();
        __syncthreads();
        const uint32_t stg = (uint32_t)((kt & 1) * KV_STG);

        // ---- S = Q @ K^T (warp: 16 rows x 32 cols, k=128) ----
        float cs[4][4];
#pragma unroll
        for (int nt = 0; nt < 4; nt++)
#pragma unroll
            for (int q = 0; q < 4; q++) cs[nt][q] = 0.0f;
#pragma unroll
        for (int k16 = 0; k16 < 8; k16++) {
            const uint32_t ko = k16 * 32;
            uint32_t Ahf[4], Alf[4];
            ldm_x4(Ahf, qbH + ko);
            ldm_x4(Alf, qbL + ko);
            uint32_t Bh[4][2], Bl[4][2];
#pragma unroll
            for (int ntp = 0; ntp < 2; ntp++) {
                uint32_t t[4];
                ldm_x4(t, kbH[ntp] + stg + ko);
                Bh[2 * ntp][0] = t[0]; Bh[2 * ntp][1] = t[1];
                Bh[2 * ntp + 1][0] = t[2]; Bh[2 * ntp + 1][1] = t[3];
                ldm_x4(t, kbL[ntp] + stg + ko);
                Bl[2 * ntp][0] = t[0]; Bl[2 * ntp][1] = t[1];
                Bl[2 * ntp + 1][0] = t[2]; Bl[2 * ntp + 1][1] = t[3];
            }
#pragma unroll
            for (int nt = 0; nt < 4; nt++) {
                mma16816(cs[nt], Ahf, Bh[nt][0], Bh[nt][1]);
                mma16816(cs[nt], Ahf, Bl[nt][0], Bl[nt][1]);
                mma16816(cs[nt], Alf, Bh[nt][0], Bh[nt][1]);
            }
        }

        // scale + mask + partial row max
        float m0 = -INFINITY, m1 = -INFINITY;
#pragma unroll
        for (int nt = 0; nt < 4; nt++) {
            int cb = nh + nt * 8 + 2 * tig;
            float mk0 = mrow[k0 + cb], mk1 = mrow[k0 + cb + 1];
            cs[nt][0] = cs[nt][0] * scale + mk0;
            cs[nt][1] = cs[nt][1] * scale + mk1;
            cs[nt][2] = cs[nt][2] * scale + mk0;
            cs[nt][3] = cs[nt][3] * scale + mk1;
            m0 = fmaxf(m0, fmaxf(cs[nt][0], cs[nt][1]));
            m1 = fmaxf(m1, fmaxf(cs[nt][2], cs[nt][3]));
        }
        m0 = fmaxf(m0, __shfl_xor_sync(0xffffffffu, m0, 1));
        m0 = fmaxf(m0, __shfl_xor_sync(0xffffffffu, m0, 2));
        m1 = fmaxf(m1, __shfl_xor_sync(0xffffffffu, m1, 1));
        m1 = fmaxf(m1, __shfl_xor_sync(0xffffffffu, m1, 2));
        if (tig == 0) {
            pmax[(warp & 1) * 64 + qm + g] = m0;
            pmax[(warp & 1) * 64 + qm + 8 + g] = m1;
        }
        __syncthreads();
        if (tid < 64) {
            float mo = s_m[tid];
            float mn = fmaxf(mo, fmaxf(pmax[tid], pmax[64 + tid]));
            s_al[tid] = __expf(mo - mn);
            s_m[tid] = mn;
        }
        __syncthreads();

        // exp, write split P, partial row sums
        {
            float mn0 = s_m[qm + g], mn1 = s_m[qm + 8 + g];
            float sum0 = 0.0f, sum1 = 0.0f;
#pragma unroll
            for (int nt = 0; nt < 4; nt++) {
                int col = nh + nt * 8 + 2 * tig;
                float p00 = __expf(cs[nt][0] - mn0);
                float p01 = __expf(cs[nt][1] - mn0);
                float p10 = __expf(cs[nt][2] - mn1);
                float p11 = __expf(cs[nt][3] - mn1);
                sum0 += p00 + p01;
                sum1 += p10 + p11;
                unsigned short h0, h1, l0, l1;
                split2(p00, h0, l0); split2(p01, h1, l1);
                *(uint32_t*)&sPh[(qm + g) * VLD + col] = pk(h0, h1);
                *(uint32_t*)&sPl[(qm + g) * VLD + col] = pk(l0, l1);
                split2(p10, h0, l0); split2(p11, h1, l1);
                *(uint32_t*)&sPh[(qm + 8 + g) * VLD + col] = pk(h0, h1);
                *(uint32_t*)&sPl[(qm + 8 + g) * VLD + col] = pk(l0, l1);
            }
            sum0 += __shfl_xor_sync(0xffffffffu, sum0, 1);
            sum0 += __shfl_xor_sync(0xffffffffu, sum0, 2);
            sum1 += __shfl_xor_sync(0xffffffffu, sum1, 1);
            sum1 += __shfl_xor_sync(0xffffffffu, sum1, 2);
            if (tig == 0) {
                psum[(warp & 1) * 64 + qm + g] = sum0;
                psum[(warp & 1) * 64 + qm + 8 + g] = sum1;
            }
        }
        __syncthreads();
        if (tid < 64)
            s_l[tid] = s_l[tid] * s_al[tid] + psum[tid] + psum[64 + tid];

        // ---- rescale O then O += P @ V (warp: 32 rows x 32 cols, k=64) ----
#pragma unroll
        for (int mt = 0; mt < 2; mt++) {
            float a0 = s_al[om + mt * 16 + g];
            float a1 = s_al[om + mt * 16 + 8 + g];
#pragma unroll
            for (int nt = 0; nt < 4; nt++) {
                co[mt][nt][0] *= a0; co[mt][nt][1] *= a0;
                co[mt][nt][2] *= a1; co[mt][nt][3] *= a1;
            }
        }
#pragma unroll
        for (int k16 = 0; k16 < 4; k16++) {
            const uint32_t vko = stg + k16 * K16_STRIDE;
            uint32_t Bh[4][2], Bl[4][2];
#pragma unroll
            for (int ntp = 0; ntp < 2; ntp++) {
                uint32_t t[4];
                ldm_x4_t(t, vbH[ntp] + vko);
                Bh[2 * ntp][0] = t[0]; Bh[2 * ntp][1] = t[1];
                Bh[2 * ntp + 1][0] = t[2]; Bh[2 * ntp + 1][1] = t[3];
                ldm_x4_t(t, vbL[ntp] + vko);
                Bl[2 * ntp][0] = t[0]; Bl[2 * ntp][1] = t[1];
                Bl[2 * ntp + 1][0] = t[2]; Bl[2 * ntp + 1][1] = t[3];
            }
            const uint32_t pko = k16 * 32;
#pragma unroll
            for (int mt = 0; mt < 2; mt++) {
                uint32_t Ahf[4], Alf[4];
                ldm_x4(Ahf, pbH[mt] + pko);
                ldm_x4(Alf, pbL[mt] + pko);
#pragma unroll
                for (int nt = 0; nt < 4; nt++) {
                    mma16816(co[mt][nt], Ahf, Bh[nt][0], Bh[nt][1]);
                    mma16816(co[mt][nt], Ahf, Bl[nt][0], Bl[nt][1]);
                    mma16816(co[mt][nt], Alf, Bh[nt][0], Bh[nt][1]);
                }
            }
        }
        __syncthreads();
    }

    // finalize: O / l -> split bf16 ctx [B*S, HID], cols h*128 + d
#pragma unroll
    for (int mt = 0; mt < 2; mt++) {
        int r0 = om + mt * 16 + g;
        int r1 = r0 + 8;
        float inv0 = 1.0f / s_l[r0];
        float inv1 = 1.0f / s_l[r1];
#pragma unroll
        for (int nt = 0; nt < 4; nt++) {
            int col = h * HD + on + nt * 8 + 2 * tig;
            size_t base0 = (size_t)(b * SEQ + q0 + r0) * HID + col;
            size_t base1 = (size_t)(b * SEQ + q0 + r1) * HID + col;
            unsigned short h0, h1, l0, l1;
            split2(co[mt][nt][0] * inv0, h0, l0);
            split2(co[mt][nt][1] * inv0, h1, l1);
            *(uint32_t*)&g_ctx_h[base0] = pk(h0, h1);
            *(uint32_t*)&g_ctx_l[base0] = pk(l0, l1);
            split2(co[mt][nt][2] * inv1, h0, l0);
            split2(co[mt][nt][3] * inv1, h1, l1);
            *(uint32_t*)&g_ctx_h[base1] = pk(h0, h1);
            *(uint32_t*)&g_ctx_l[base1] = pk(l0, l1);
        }
    }
}

// ---------------- launcher ---------------------------------------------------
extern "C" void kernel_launch(void* const* d_in, const int* in_sizes, int n_in,
                              void* d_out, int out_size) {
    const float* hidden = (const float*)d_in[0];
    const float* mask   = (const float*)d_in[1];
    const float* Wqkv   = (const float*)d_in[2];
    const float* bqkv   = (const float*)d_in[3];
    const float* Wout   = (const float*)d_in[4];
    const float* bout   = (const float*)d_in[5];
    float* out = (float*)d_out;

    // one-time splits (~25M elems total)
    split_kernel<<<(MROWS * HID / 4 + 255) / 256, 256>>>(hidden, 0, MROWS * HID / 4);
    split_kernel<<<(NQKV * HID / 4 + 255) / 256, 256>>>(Wqkv, 1, NQKV * HID / 4);
    split_kernel<<<(HID * HID / 4 + 255) / 256, 256>>>(Wout, 2, HID * HID / 4);
    rope_table_kernel<<<512, 256>>>();

    const int gemm_smem = 2 * 128 * GLD * 4 * 2;   // 81920 B
    cudaFuncSetAttribute(mma_gemm_kernel<0>,
                         cudaFuncAttributeMaxDynamicSharedMemorySize, gemm_smem);
    cudaFuncSetAttribute(mma_gemm_kernel<1>,
                         cudaFuncAttributeMaxDynamicSharedMemorySize, gemm_smem);

    mma_gemm_kernel<0><<<dim3(48, 32), 256, gemm_smem>>>(bqkv, nullptr);

    cudaFuncSetAttribute(attn_mma_kernel,
                         cudaFuncAttributeMaxDynamicSharedMemorySize, ATTN_SMEM);
    attn_mma_kernel<<<dim3(SEQ / 64, NH, BATCH), 256, ATTN_SMEM>>>(mask);

    mma_gemm_kernel<1><<<dim3(16, 32), 256, gemm_smem>>>(bout, out);
}

// round 14
// speedup vs baseline: 3.1298x; 1.0608x over previous
#include <cuda_runtime.h>
#include <cuda_bf16.h>
#include <math.h>
#include <stdint.h>

#define BATCH 2
#define SEQ   2048
#define NH    16
#define HD    128
#define HID   2048
#define NQKV  6144
#define MROWS 4096   // B*S
#define QKV_ELEMS ((size_t)BATCH * NH * SEQ * HD)

// ---------------- scratch (static device globals; no runtime alloc) ----------
__device__ unsigned short g_hid_h[(size_t)MROWS * HID], g_hid_l[(size_t)MROWS * HID];
__device__ unsigned short g_wqkv_h[(size_t)NQKV * HID], g_wqkv_l[(size_t)NQKV * HID];
__device__ unsigned short g_wout_h[(size_t)HID * HID], g_wout_l[(size_t)HID * HID];
__device__ unsigned short g_q_h[QKV_ELEMS], g_q_l[QKV_ELEMS];
__device__ unsigned short g_k_h[QKV_ELEMS], g_k_l[QKV_ELEMS];
__device__ unsigned short g_v_h[QKV_ELEMS], g_v_l[QKV_ELEMS];
__device__ unsigned short g_ctx_h[(size_t)MROWS * HID], g_ctx_l[(size_t)MROWS * HID];
__device__ float g_cos[SEQ * 64], g_sin[SEQ * 64];

// ---------------- helpers ----------------------------------------------------
__device__ __forceinline__ uint32_t smem_u32(const void* p) {
    return (uint32_t)__cvta_generic_to_shared(p);
}
__device__ __forceinline__ void ldm_x4(uint32_t (&r)[4], uint32_t addr) {
    asm volatile("ldmatrix.sync.aligned.m8n8.x4.shared.b16 {%0,%1,%2,%3}, [%4];\n"
        : "=r"(r[0]), "=r"(r[1]), "=r"(r[2]), "=r"(r[3]) : "r"(addr));
}
__device__ __forceinline__ void ldm_x4_t(uint32_t (&r)[4], uint32_t addr) {
    asm volatile("ldmatrix.sync.aligned.m8n8.x4.trans.shared.b16 {%0,%1,%2,%3}, [%4];\n"
        : "=r"(r[0]), "=r"(r[1]), "=r"(r[2]), "=r"(r[3]) : "r"(addr));
}
__device__ __forceinline__ void mma16816(float (&c)[4], const uint32_t (&a)[4],
                                         uint32_t b0, uint32_t b1) {
    asm volatile(
        "mma.sync.aligned.m16n8k16.row.col.f32.bf16.bf16.f32 "
        "{%0,%1,%2,%3}, {%4,%5,%6,%7}, {%8,%9}, {%0,%1,%2,%3};\n"
        : "+f"(c[0]), "+f"(c[1]), "+f"(c[2]), "+f"(c[3])
        : "r"(a[0]), "r"(a[1]), "r"(a[2]), "r"(a[3]), "r"(b0), "r"(b1));
}
__device__ __forceinline__ void split2(float x, unsigned short& h, unsigned short& l) {
    __nv_bfloat16 bh = __float2bfloat16_rn(x);
    h = __bfloat16_as_ushort(bh);
    l = __bfloat16_as_ushort(__float2bfloat16_rn(x - __bfloat162float(bh)));
}
__device__ __forceinline__ uint32_t pk(unsigned short a, unsigned short b) {
    return (uint32_t)a | ((uint32_t)b << 16);
}
__device__ __forceinline__ uint32_t pkf(float a, float b) {
    unsigned short ha, la, hb, lb;
    split2(a, ha, la); split2(b, hb, lb);
    (void)la; (void)lb;
    return pk(ha, hb);
}
__device__ __forceinline__ void cp16(uint32_t s, const void* g) {
    asm volatile("cp.async.cg.shared.global [%0], [%1], 16;\n" :: "r"(s), "l"(g));
}
__device__ __forceinline__ void cp_commit() {
    asm volatile("cp.async.commit_group;\n");
}
template <int N> __device__ __forceinline__ void cp_wait() {
    asm volatile("cp.async.wait_group %0;\n" :: "n"(N));
}

// ---------------- one-time fp32 -> bf16 hi/lo split --------------------------
__global__ void split_kernel(const float* __restrict__ src, int sel, int n4) {
    int i = blockIdx.x * 256 + threadIdx.x;
    if (i >= n4) return;
    unsigned short *dh, *dl;
    if (sel == 0)      { dh = g_hid_h;  dl = g_hid_l;  }
    else if (sel == 1) { dh = g_wqkv_h; dl = g_wqkv_l; }
    else               { dh = g_wout_h; dl = g_wout_l; }
    float4 v = ((const float4*)src)[i];
    unsigned short h0, h1, h2, h3, l0, l1, l2, l3;
    split2(v.x, h0, l0); split2(v.y, h1, l1);
    split2(v.z, h2, l2); split2(v.w, h3, l3);
    ((uint2*)dh)[i] = make_uint2(pk(h0, h1), pk(h2, h3));
    ((uint2*)dl)[i] = make_uint2(pk(l0, l1), pk(l2, l3));
}

// ---------------- RoPE tables ------------------------------------------------
__global__ void rope_table_kernel() {
    int idx = blockIdx.x * 256 + threadIdx.x;
    if (idx >= SEQ * 64) return;
    int s = idx >> 6, i = idx & 63;
    float inv = powf(10000.0f, -(float)(2 * i) / 128.0f);
    float ang = (float)s * inv;
    g_cos[idx] = cosf(ang);
    g_sin[idx] = sinf(ang);
}

// ---------------- split-bf16 tensor GEMM, cp.async double-buffered -----------
// (round-11 passing version, unchanged)
#define GLD 40

template <int EPI>
__global__ __launch_bounds__(256, 1) void mma_gemm_kernel(
    const float* __restrict__ bias, float* __restrict__ out) {
    extern __shared__ unsigned short sm[];
    unsigned short* sAh = sm;
    unsigned short* sAl = sAh + 2 * 128 * GLD;
    unsigned short* sBh = sAl + 2 * 128 * GLD;
    unsigned short* sBl = sBh + 2 * 128 * GLD;

    const unsigned short *Ah_g, *Al_g, *Bh_g, *Bl_g;
    if (EPI == 0) { Ah_g = g_hid_h; Al_g = g_hid_l; Bh_g = g_wqkv_h; Bl_g = g_wqkv_l; }
    else          { Ah_g = g_ctx_h; Al_g = g_ctx_l; Bh_g = g_wout_h; Bl_g = g_wout_l; }

    const int tid = threadIdx.x;
    const int warp = tid >> 5, lane = tid & 31;
    const int g = lane >> 2, tig = lane & 3;
    const int wm = (warp >> 2) * 64, wn = (warp & 3) * 32;
    const int bm = blockIdx.y * 128, bn = blockIdx.x * 128;

    float c[4][4][4];
#pragma unroll
    for (int mt = 0; mt < 4; mt++)
#pragma unroll
        for (int nt = 0; nt < 4; nt++)
#pragma unroll
            for (int q = 0; q < 4; q++) c[mt][nt][q] = 0.0f;

    uint32_t aH[4], aL[4];
#pragma unroll
    for (int mt = 0; mt < 4; mt++) {
        int r = wm + mt * 16 + (lane & 15);
        int cc = (lane >> 4) << 3;
        aH[mt] = smem_u32(&sAh[r * GLD + cc]);
        aL[mt] = smem_u32(&sAl[r * GLD + cc]);
    }
    uint32_t bH[2], bL[2];
#pragma unroll
    for (int ntp = 0; ntp < 2; ntp++) {
        int r = wn + ntp * 16 + (lane & 7) + ((lane >> 4) << 3);
        int cc = ((lane >> 3) & 1) << 3;
        bH[ntp] = smem_u32(&sBh[r * GLD + cc]);
        bL[ntp] = smem_u32(&sBl[r * GLD + cc]);
    }

    auto load_stage = [&](int st, int k0) {
        int off = st * 128 * GLD;
#pragma unroll
        for (int i = 0; i < 2; i++) {
            int cch = tid + i * 256;
            int r = cch >> 2, col = (cch & 3) << 3;
            size_t ga = (size_t)(bm + r) * HID + k0 + col;
            size_t gb = (size_t)(bn + r) * HID + k0 + col;
            int so = off + r * GLD + col;
            cp16(smem_u32(&sAh[so]), Ah_g + ga);
            cp16(smem_u32(&sAl[so]), Al_g + ga);
            cp16(smem_u32(&sBh[so]), Bh_g + gb);
            cp16(smem_u32(&sBl[so]), Bl_g + gb);
        }
    };

    load_stage(0, 0);
    cp_commit();

#pragma unroll 1
    for (int kt = 0; kt < HID / 32; kt++) {
        if (kt + 1 < HID / 32) load_stage((kt + 1) & 1, (kt + 1) * 32);
        cp_commit();
        cp_wait<1>();
        __syncthreads();

        const uint32_t stb = (uint32_t)((kt & 1) * 128 * GLD * 2);
#pragma unroll
        for (int ks = 0; ks < 2; ks++) {
            const uint32_t ko = stb + ks * 32;
            uint32_t Ah[4][4], Al[4][4];
#pragma unroll
            for (int mt = 0; mt < 4; mt++) {
                ldm_x4(Ah[mt], aH[mt] + ko);
                ldm_x4(Al[mt], aL[mt] + ko);
            }
            uint32_t Bh[4][2], Bl[4][2];
#pragma unroll
            for (int ntp = 0; ntp < 2; ntp++) {
                uint32_t t[4];
                ldm_x4(t, bH[ntp] + ko);
                Bh[2 * ntp][0] = t[0]; Bh[2 * ntp][1] = t[1];
                Bh[2 * ntp + 1][0] = t[2]; Bh[2 * ntp + 1][1] = t[3];
                ldm_x4(t, bL[ntp] + ko);
                Bl[2 * ntp][0] = t[0]; Bl[2 * ntp][1] = t[1];
                Bl[2 * ntp + 1][0] = t[2]; Bl[2 * ntp + 1][1] = t[3];
            }
#pragma unroll
            for (int mt = 0; mt < 4; mt++)
#pragma unroll
                for (int nt = 0; nt < 4; nt++) {
                    mma16816(c[mt][nt], Ah[mt], Bh[nt][0], Bh[nt][1]);
                    mma16816(c[mt][nt], Ah[mt], Bl[nt][0], Bl[nt][1]);
                    mma16816(c[mt][nt], Al[mt], Bh[nt][0], Bh[nt][1]);
                }
        }
        __syncthreads();
    }

#pragma unroll
    for (int nt = 0; nt < 4; nt++) {
        const int n0 = bn + wn + nt * 8 + 2 * tig;
        const float bv0 = bias[n0], bv1 = bias[n0 + 1];
#pragma unroll
        for (int mt = 0; mt < 4; mt++) {
#pragma unroll
            for (int half = 0; half < 2; half++) {
                int gm = bm + wm + mt * 16 + g + half * 8;
                float v0 = c[mt][nt][half * 2 + 0] + bv0;
                float v1 = c[mt][nt][half * 2 + 1] + bv1;
                if (EPI == 0) {
                    int seg = n0 >> 11;
                    int h = (n0 >> 7) & 15;
                    int d0 = n0 & 127;
                    int b = gm >> 11, s = gm & 2047;
                    unsigned short *dh, *dl;
                    if (seg < 2) {
                        float cc = g_cos[s * 64 + (d0 >> 1)];
                        float ss = g_sin[s * 64 + (d0 >> 1)];
                        float e = v0, o = v1;
                        v0 = e * cc - o * ss;
                        v1 = e * ss + o * cc;
                        if (seg == 0) { dh = g_q_h; dl = g_q_l; }
                        else          { dh = g_k_h; dl = g_k_l; }
                    } else { dh = g_v_h; dl = g_v_l; }
                    size_t off = (((size_t)b * NH + h) * SEQ + s) * HD + d0;
                    unsigned short h0, h1, l0, l1;
                    split2(v0, h0, l0); split2(v1, h1, l1);
                    *(uint32_t*)&dh[off] = pk(h0, h1);
                    *(uint32_t*)&dl[off] = pk(l0, l1);
                } else {
                    *(float2*)(out + (size_t)gm * HID + n0) = make_float2(v0, v1);
                }
            }
        }
    }
}

// ---------------- flash attention: row-owned warps, register-resident P ------
// Br=128 (8 warps x 16 rows), Bc=64, D=128. K/V double-buffered.
#define QLD 136
#define KV_STG_B (64 * QLD * 2)        // bytes per K/V stage per array
#define ATTN_SMEM ((2 * 128 * QLD + 8 * 64 * QLD) * 2)   // 208896 B

__global__ __launch_bounds__(256, 1) void attn_mma_kernel(const float* __restrict__ mask) {
    extern __shared__ unsigned short asm_[];
    unsigned short* sQh = asm_;                       // [128][QLD]
    unsigned short* sQl = sQh + 128 * QLD;
    unsigned short* sKh = sQl + 128 * QLD;            // [2][64][QLD]
    unsigned short* sKl = sKh + 2 * 64 * QLD;
    unsigned short* sVh = sKl + 2 * 64 * QLD;         // [2][64][QLD] natural [s][d]
    unsigned short* sVl = sVh + 2 * 64 * QLD;

    const int tid = threadIdx.x;
    const int warp = tid >> 5, lane = tid & 31;
    const int g = lane >> 2, tig = lane & 3;
    const int q0 = blockIdx.x * 128;
    const int h = blockIdx.y, b = blockIdx.z;
    const size_t head_base = ((size_t)b * NH + h) * SEQ * HD;
    const float scale = 0.08838834764831845f;

    // Q load (group 0): 128 rows x 128 cols, hi+lo
#pragma unroll
    for (int i = 0; i < 8; i++) {
        int cch = tid + i * 256;                      // 0..2047
        int r = cch >> 4, col = (cch & 15) << 3;
        size_t ga = head_base + (size_t)(q0 + r) * HD + col;
        cp16(smem_u32(&sQh[r * QLD + col]), g_q_h + ga);
        cp16(smem_u32(&sQl[r * QLD + col]), g_q_l + ga);
    }
    cp_commit();

    auto load_kv = [&](int st, int k0) {
        int off = st * 64 * QLD;
#pragma unroll
        for (int i = 0; i < 4; i++) {
            int cch = tid + i * 256;                  // 0..1023
            int r = cch >> 4, col = (cch & 15) << 3;
            size_t ga = head_base + (size_t)(k0 + r) * HD + col;
            int so = off + r * QLD + col;
            cp16(smem_u32(&sKh[so]), g_k_h + ga);
            cp16(smem_u32(&sKl[so]), g_k_l + ga);
            cp16(smem_u32(&sVh[so]), g_v_h + ga);
            cp16(smem_u32(&sVl[so]), g_v_l + ga);
        }
    };
    load_kv(0, 0);
    cp_commit();

    // ldmatrix bases
    const uint32_t qbH = smem_u32(&sQh[(warp * 16 + (lane & 15)) * QLD + ((lane >> 4) << 3)]);
    const uint32_t qbL = smem_u32(&sQl[(warp * 16 + (lane & 15)) * QLD + ((lane >> 4) << 3)]);
    uint32_t kbH[4], kbL[4], vbH[8], vbL[8];
#pragma unroll
    for (int ntp = 0; ntp < 4; ntp++) {
        int r = ntp * 16 + (lane & 7) + ((lane >> 4) << 3);
        int cc = ((lane >> 3) & 1) << 3;
        kbH[ntp] = smem_u32(&sKh[r * QLD + cc]);
        kbL[ntp] = smem_u32(&sKl[r * QLD + cc]);
    }
#pragma unroll
    for (int j = 0; j < 8; j++) {
        int vr = lane & 15;
        int vc = j * 16 + ((lane >> 4) << 3);
        vbH[j] = smem_u32(&sVh[vr * QLD + vc]);
        vbL[j] = smem_u32(&sVl[vr * QLD + vc]);
    }

    float co[16][4];
#pragma unroll
    for (int nt = 0; nt < 16; nt++)
#pragma unroll
        for (int q = 0; q < 4; q++) co[nt][q] = 0.0f;
    float m0 = -INFINITY, m1 = -INFINITY, l0 = 0.0f, l1 = 0.0f;

    const float* mrow = mask + (size_t)b * SEQ;

#pragma unroll 1
    for (int kt = 0; kt < SEQ / 64; kt++) {
        const int k0 = kt * 64;
        __syncthreads();   // all warps done reading the stage about to be overwritten
        if (kt + 1 < SEQ / 64) load_kv((kt + 1) & 1, (kt + 1) * 64);
        cp_commit();
        cp_wait<1>();      // current stage (committed last iter) landed
        __syncthreads();   // its data visible to all warps
        const uint32_t stg = (uint32_t)((kt & 1) * KV_STG_B);

        // ---- S = Q @ K^T (warp: 16 rows x 64 cols, k=128) ----
        float cs[8][4];
#pragma unroll
        for (int nt = 0; nt < 8; nt++)
#pragma unroll
            for (int q = 0; q < 4; q++) cs[nt][q] = 0.0f;
#pragma unroll
        for (int k16 = 0; k16 < 8; k16++) {
            const uint32_t ko = k16 * 32;
            uint32_t Ahf[4], Alf[4];
            ldm_x4(Ahf, qbH + ko);
            ldm_x4(Alf, qbL + ko);
            uint32_t Bh[8][2], Bl[8][2];
#pragma unroll
            for (int ntp = 0; ntp < 4; ntp++) {
                uint32_t t[4];
                ldm_x4(t, kbH[ntp] + stg + ko);
                Bh[2 * ntp][0] = t[0]; Bh[2 * ntp][1] = t[1];
                Bh[2 * ntp + 1][0] = t[2]; Bh[2 * ntp + 1][1] = t[3];
                ldm_x4(t, kbL[ntp] + stg + ko);
                Bl[2 * ntp][0] = t[0]; Bl[2 * ntp][1] = t[1];
                Bl[2 * ntp + 1][0] = t[2]; Bl[2 * ntp + 1][1] = t[3];
            }
#pragma unroll
            for (int nt = 0; nt < 8; nt++) {
                mma16816(cs[nt], Ahf, Bh[nt][0], Bh[nt][1]);
                mma16816(cs[nt], Ahf, Bl[nt][0], Bl[nt][1]);
                mma16816(cs[nt], Alf, Bh[nt][0], Bh[nt][1]);
            }
        }

        // ---- scale + mask + warp-local online softmax ----
        float mx0 = -INFINITY, mx1 = -INFINITY;
#pragma unroll
        for (int nt = 0; nt < 8; nt++) {
            int cb = nt * 8 + 2 * tig;
            float mk0 = mrow[k0 + cb], mk1 = mrow[k0 + cb + 1];
            cs[nt][0] = cs[nt][0] * scale + mk0;
            cs[nt][1] = cs[nt][1] * scale + mk1;
            cs[nt][2] = cs[nt][2] * scale + mk0;
            cs[nt][3] = cs[nt][3] * scale + mk1;
            mx0 = fmaxf(mx0, fmaxf(cs[nt][0], cs[nt][1]));
            mx1 = fmaxf(mx1, fmaxf(cs[nt][2], cs[nt][3]));
        }
        mx0 = fmaxf(mx0, __shfl_xor_sync(0xffffffffu, mx0, 1));
        mx0 = fmaxf(mx0, __shfl_xor_sync(0xffffffffu, mx0, 2));
        mx1 = fmaxf(mx1, __shfl_xor_sync(0xffffffffu, mx1, 1));
        mx1 = fmaxf(mx1, __shfl_xor_sync(0xffffffffu, mx1, 2));
        const float mn0 = fmaxf(m0, mx0), mn1 = fmaxf(m1, mx1);
        const float al0 = __expf(m0 - mn0), al1 = __expf(m1 - mn1);
        m0 = mn0; m1 = mn1;

        float sum0 = 0.0f, sum1 = 0.0f;
#pragma unroll
        for (int nt = 0; nt < 8; nt++) {
            cs[nt][0] = __expf(cs[nt][0] - mn0);
            cs[nt][1] = __expf(cs[nt][1] - mn0);
            cs[nt][2] = __expf(cs[nt][2] - mn1);
            cs[nt][3] = __expf(cs[nt][3] - mn1);
            sum0 += cs[nt][0] + cs[nt][1];
            sum1 += cs[nt][2] + cs[nt][3];
        }
        sum0 += __shfl_xor_sync(0xffffffffu, sum0, 1);
        sum0 += __shfl_xor_sync(0xffffffffu, sum0, 2);
        sum1 += __shfl_xor_sync(0xffffffffu, sum1, 1);
        sum1 += __shfl_xor_sync(0xffffffffu, sum1, 2);
        l0 = l0 * al0 + sum0;
        l1 = l1 * al1 + sum1;

        // ---- rescale O, then O += P @ V (P stays in registers) ----
#pragma unroll
        for (int nt = 0; nt < 16; nt++) {
            co[nt][0] *= al0; co[nt][1] *= al0;
            co[nt][2] *= al1; co[nt][3] *= al1;
        }
#pragma unroll
        for (int kb = 0; kb < 4; kb++) {
            // P fragment from C fragments of tiles 2kb, 2kb+1 (hi and lo splits)
            uint32_t paH[4], paL[4];
            {
                unsigned short h0, h1, l0s, l1s;
                split2(cs[2 * kb][0], h0, l0s); split2(cs[2 * kb][1], h1, l1s);
                paH[0] = pk(h0, h1); paL[0] = pk(l0s, l1s);
                split2(cs[2 * kb][2], h0, l0s); split2(cs[2 * kb][3], h1, l1s);
                paH[1] = pk(h0, h1); paL[1] = pk(l0s, l1s);
                split2(cs[2 * kb + 1][0], h0, l0s); split2(cs[2 * kb + 1][1], h1, l1s);
                paH[2] = pk(h0, h1); paL[2] = pk(l0s, l1s);
                split2(cs[2 * kb + 1][2], h0, l0s); split2(cs[2 * kb + 1][3], h1, l1s);
                paH[3] = pk(h0, h1); paL[3] = pk(l0s, l1s);
            }
            const uint32_t vko = stg + (uint32_t)kb * 16 * QLD * 2;
#pragma unroll
            for (int half = 0; half < 2; half++) {
                uint32_t Bh[8][2], Bl[8][2];
#pragma unroll
                for (int jp = 0; jp < 4; jp++) {
                    uint32_t t[4];
                    ldm_x4_t(t, vbH[half * 4 + jp] + vko);
                    Bh[2 * jp][0] = t[0]; Bh[2 * jp][1] = t[1];
                    Bh[2 * jp + 1][0] = t[2]; Bh[2 * jp + 1][1] = t[3];
                    ldm_x4_t(t, vbL[half * 4 + jp] + vko);
                    Bl[2 * jp][0] = t[0]; Bl[2 * jp][1] = t[1];
                    Bl[2 * jp + 1][0] = t[2]; Bl[2 * jp + 1][1] = t[3];
                }
#pragma unroll
                for (int nt = 0; nt < 8; nt++) {
                    int ng = half * 8 + nt;
                    mma16816(co[ng], paH, Bh[nt][0], Bh[nt][1]);
                    mma16816(co[ng], paH, Bl[nt][0], Bl[nt][1]);
                    mma16816(co[ng], paL, Bh[nt][0], Bh[nt][1]);
                }
            }
        }
    }

    // ---- finalize: O / l -> split bf16 ctx [B*S, HID], cols h*128 + d ----
    const float inv0 = 1.0f / l0, inv1 = 1.0f / l1;
    const int r0 = warp * 16 + g, r1 = r0 + 8;
#pragma unroll
    for (int nt = 0; nt < 16; nt++) {
        int col = h * HD + nt * 8 + 2 * tig;
        size_t base0 = (size_t)(b * SEQ + q0 + r0) * HID + col;
        size_t base1 = (size_t)(b * SEQ + q0 + r1) * HID + col;
        unsigned short h0, h1, l0s, l1s;
        split2(co[nt][0] * inv0, h0, l0s);
        split2(co[nt][1] * inv0, h1, l1s);
        *(uint32_t*)&g_ctx_h[base0] = pk(h0, h1);
        *(uint32_t*)&g_ctx_l[base0] = pk(l0s, l1s);
        split2(co[nt][2] * inv1, h0, l0s);
        split2(co[nt][3] * inv1, h1, l1s);
        *(uint32_t*)&g_ctx_h[base1] = pk(h0, h1);
        *(uint32_t*)&g_ctx_l[base1] = pk(l0s, l1s);
    }
}

// ---------------- launcher ---------------------------------------------------
extern "C" void kernel_launch(void* const* d_in, const int* in_sizes, int n_in,
                              void* d_out, int out_size) {
    const float* hidden = (const float*)d_in[0];
    const float* mask   = (const float*)d_in[1];
    const float* Wqkv   = (const float*)d_in[2];
    const float* bqkv   = (const float*)d_in[3];
    const float* Wout   = (const float*)d_in[4];
    const float* bout   = (const float*)d_in[5];
    float* out = (float*)d_out;

    split_kernel<<<(MROWS * HID / 4 + 255) / 256, 256>>>(hidden, 0, MROWS * HID / 4);
    split_kernel<<<(NQKV * HID / 4 + 255) / 256, 256>>>(Wqkv, 1, NQKV * HID / 4);
    split_kernel<<<(HID * HID / 4 + 255) / 256, 256>>>(Wout, 2, HID * HID / 4);
    rope_table_kernel<<<512, 256>>>();

    const int gemm_smem = 2 * 128 * GLD * 4 * 2;   // 81920 B
    cudaFuncSetAttribute(mma_gemm_kernel<0>,
                         cudaFuncAttributeMaxDynamicSharedMemorySize, gemm_smem);
    cudaFuncSetAttribute(mma_gemm_kernel<1>,
                         cudaFuncAttributeMaxDynamicSharedMemorySize, gemm_smem);

    mma_gemm_kernel<0><<<dim3(48, 32), 256, gemm_smem>>>(bqkv, nullptr);

    cudaFuncSetAttribute(attn_mma_kernel,
                         cudaFuncAttributeMaxDynamicSharedMemorySize, ATTN_SMEM);
    attn_mma_kernel<<<dim3(SEQ / 128, NH, BATCH), 256, ATTN_SMEM>>>(mask);

    mma_gemm_kernel<1><<<dim3(16, 32), 256, gemm_smem>>>(bout, out);
}